// round 8
// baseline (speedup 1.0000x reference)
#include <cuda_runtime.h>
#include <cstdint>
#include <float.h>
#include <limits.h>

// Problem constants (fixed shapes)
#define B_    8
#define C_    16
#define F_    256
#define H_    112
#define W_    112
#define NCELL (B_ * C_)       // 128
#define W4_   (W_ / 4)        // 28 float4 per feature row
#define PXPC  (H_ * W_)       // 12544 pixels per cell

// Compact mask scratch bounds: bbox w <= 35, +3 align +3 pad -> <= 40; h <= 35
#define MAXBW 40
#define MAXBH 36
#define CMSTRIDE (MAXBW * MAXBH)   // 1440 floats

// Max rows a single y-phase can span: ceil(35/3)+1 = 13
#define MAXPH 14
#define SMSK  (MAXPH * MAXBW)      // 560 floats

// Per-cell header: y0, szy, x0a, bwa, x0off, szx
__device__ int g_hdr[NCELL][8];
// Per-cell compact float mask (1.0 / 0.0), row stride bwa, 16B aligned rows
__device__ __align__(16) float g_cmask[NCELL][CMSTRIDE];

// ---------------------------------------------------------------------------
// Fused prep: per-cell dtype detect + bbox + compact float mask. 1 block/cell.
__global__ void __launch_bounds__(256) prep_k(const void* __restrict__ mask) {
    const int cell = blockIdx.x;
    const int t = threadIdx.x;

    __shared__ int sy0, sy1, sx0, sx1;
    if (t == 0) { sy0 = INT_MAX; sy1 = -1; sx0 = INT_MAX; sx1 = -1; }

    // --- detect dtype over this cell's 12544-byte window (784 uint4) ---
    int r = 0;
    {
        const uint4* wq = (const uint4*)mask + (size_t)cell * 784;
        for (int i = t; i < 784; i += 256) {
            uint4 w = wq[i];
            if ((w.x != 0x3F800000u && (w.x & 0xFFFFFF00u)) ||
                (w.y != 0x3F800000u && (w.y & 0xFFFFFF00u)) ||
                (w.z != 0x3F800000u && (w.z & 0xFFFFFF00u)) ||
                (w.w != 0x3F800000u && (w.w & 0xFFFFFF00u))) r = 1;
        }
    }
    const int flag = __syncthreads_or(r);

    // --- bbox scan ---
    int ly0 = INT_MAX, ly1 = -1, lx0 = INT_MAX, lx1 = -1;
    if (flag) {
        const uint4* mq = (const uint4*)mask + (size_t)cell * 784;
        for (int i = t; i < 784; i += 256) {
            uint4 w = mq[i];
            if (w.x | w.y | w.z | w.w) {
                int p = i * 16, y = p / W_, xb = p % W_;
                ly0 = min(ly0, y); ly1 = max(ly1, y);
                unsigned int comp[4] = {w.x, w.y, w.z, w.w};
#pragma unroll
                for (int c = 0; c < 4; c++) {
#pragma unroll
                    for (int k = 0; k < 4; k++) {
                        if ((comp[c] >> (k * 8)) & 0xFFu) {
                            int x = xb + c * 4 + k;
                            lx0 = min(lx0, x); lx1 = max(lx1, x);
                        }
                    }
                }
            }
        }
    } else {
        const uint4* mq = (const uint4*)mask + (size_t)cell * 3136;
        for (int i = t; i < 3136; i += 256) {
            uint4 w = mq[i];
            if (w.x | w.y | w.z | w.w) {
                int p = i * 4, y = p / W_, xb = p % W_;
                ly0 = min(ly0, y); ly1 = max(ly1, y);
                if (w.x) { lx0 = min(lx0, xb);     lx1 = max(lx1, xb);     }
                if (w.y) { lx0 = min(lx0, xb + 1); lx1 = max(lx1, xb + 1); }
                if (w.z) { lx0 = min(lx0, xb + 2); lx1 = max(lx1, xb + 2); }
                if (w.w) { lx0 = min(lx0, xb + 3); lx1 = max(lx1, xb + 3); }
            }
        }
    }
    if (ly1 >= 0) {
        atomicMin(&sy0, ly0); atomicMax(&sy1, ly1);
        atomicMin(&sx0, lx0); atomicMax(&sx1, lx1);
    }
    __syncthreads();

    const int y0 = sy0, y1 = sy1 + 1, x0 = sx0, x1 = sx1 + 1;
    const int x0a = x0 & ~3;
    const int bwa = (x1 - x0a + 3) & ~3;
    const int bh  = y1 - y0;

    if (t == 0) {
        g_hdr[cell][0] = y0;
        g_hdr[cell][1] = bh;
        g_hdr[cell][2] = x0a;
        g_hdr[cell][3] = bwa;
        g_hdr[cell][4] = x0 - x0a;
        g_hdr[cell][5] = x1 - x0;
    }

    const int ntot = bh * bwa;
    const uint8_t* mb = (const uint8_t*)mask + (size_t)cell * PXPC;
    const int*     mi = (const int*)mask     + (size_t)cell * PXPC;
    for (int p = t; p < ntot; p += 256) {
        int rr = p / bwa, c = p - rr * bwa;
        int gp = (y0 + rr) * W_ + (x0a + c);
        bool set = flag ? (mb[gp] != 0) : (mi[gp] != 0);
        g_cmask[cell][p] = set ? 1.0f : 0.0f;
    }
}

// ---------------------------------------------------------------------------
// Main pooling. grid=(NCELL, F/32, 3 y-phases), block=128 (4 warps).
// Each half-warp (16 lanes) handles 4 feature streams (f0 + {0,8,16,24});
// each block handles ONE y-phase of one cell for 32 features. Per-warp MLP:
// 16 lanes x 4 streams = 64 outstanding LDG.128 per iteration (at the ~55
// per-warp LSU cap); occupancy raised via tighter reg budget (<=48 regs,
// 10 CTAs/SM) instead of deeper unroll.
__global__ void __launch_bounds__(128, 10) pool_k(const float* __restrict__ feat,
                                                  float* __restrict__ out) {
    const int cell  = blockIdx.x;
    const int phase = blockIdx.z;
    const int warp = threadIdx.x >> 5;
    const int lane = threadIdx.x & 31;
    const int half = lane >> 4;
    const int hlane = lane & 15;
    const int grp = warp * 2 + half;                 // 0..7
    const int f0 = blockIdx.y * 32 + grp;            // streams: f0 + {0,8,16,24}

    const int y0    = g_hdr[cell][0];
    const int szy   = g_hdr[cell][1];
    const int x0a   = g_hdr[cell][2];
    const int bwa   = g_hdr[cell][3];
    const int x0off = g_hdr[cell][4];
    const int szx   = g_hdr[cell][5];

    const int ys = (phase * szy) / 3;
    const int ye = ((phase + 1) * szy + 2) / 3;      // ceil; bins may share a row
    const int nrows = ye - ys;

    // --- stage this phase's mask rows into shared memory (vectorized) ---
    __shared__ __align__(16) float smask[SMSK];
    {
        const int nq = (nrows * bwa) >> 2;
        const float4* src = (const float4*)(g_cmask[cell] + ys * bwa);
        float4* dst = (float4*)smask;
        for (int p = threadIdx.x; p < nq; p += 128) dst[p] = src[p];
    }
    __syncthreads();

    const int nG  = bwa >> 2;          // float4 groups per row: 3..10
    const int rpi = 16 / nG;           // rows per iteration: 1..5
    const int rowoff = hlane / nG;
    const int g = hlane - rowoff * nG;
    const bool active = (rowoff < rpi);

    const int b = cell >> 4;
    const int FOFF = 8 * H_ * W4_;     // float4 offset between feature streams
    const float4* fp = (const float4*)feat
        + (size_t)((b * F_ + f0) * H_ + ys + y0 + rowoff) * W4_ + (x0a >> 2) + g;
    const float4* mp = (const float4*)smask + rowoff * nG + g;
    const int fstep = rpi * W4_;
    const int mstep = rpi * nG;

    // x-bin membership per (bin j, col k)
    bool mem[12];
#pragma unroll
    for (int j = 0; j < 3; j++)
#pragma unroll
        for (int k = 0; k < 4; k++) {
            const int relx = g * 4 + k - x0off;
            mem[j * 4 + k] = (3 * relx >= j * szx - 2) && (3 * relx < (j + 1) * szx);
        }

    float acc[4][4];
#pragma unroll
    for (int s = 0; s < 4; s++)
#pragma unroll
        for (int k = 0; k < 4; k++) acc[s][k] = -FLT_MAX;

    if (active) {
        for (int rr = rowoff; rr < nrows; rr += rpi, fp += fstep, mp += mstep) {
            const float4 mv = *mp;          // LDS.128
            float4 fv[4];
            fv[0] = __ldg(fp);
            fv[1] = __ldg(fp + FOFF);
            fv[2] = __ldg(fp + 2 * FOFF);
            fv[3] = __ldg(fp + 3 * FOFF);
#pragma unroll
            for (int s = 0; s < 4; s++) {
                acc[s][0] = fmaxf(acc[s][0], fv[s].x * mv.x);
                acc[s][1] = fmaxf(acc[s][1], fv[s].y * mv.y);
                acc[s][2] = fmaxf(acc[s][2], fv[s].z * mv.z);
                acc[s][3] = fmaxf(acc[s][3], fv[s].w * mv.w);
            }
        }
    }

    float* obase = out + (size_t)cell * (F_ * 9) + f0 * 9 + phase * 3;

    // per x-bin: merge columns, butterfly across the 16-lane group, store
#pragma unroll
    for (int j = 0; j < 3; j++) {
        float t0 = -FLT_MAX, t1 = -FLT_MAX, t2 = -FLT_MAX, t3 = -FLT_MAX;
#pragma unroll
        for (int k = 0; k < 4; k++) {
            if (mem[j * 4 + k]) {
                t0 = fmaxf(t0, acc[0][k]);
                t1 = fmaxf(t1, acc[1][k]);
                t2 = fmaxf(t2, acc[2][k]);
                t3 = fmaxf(t3, acc[3][k]);
            }
        }
#pragma unroll
        for (int o = 8; o > 0; o >>= 1) {
            t0 = fmaxf(t0, __shfl_xor_sync(0xffffffffu, t0, o));
            t1 = fmaxf(t1, __shfl_xor_sync(0xffffffffu, t1, o));
            t2 = fmaxf(t2, __shfl_xor_sync(0xffffffffu, t2, o));
            t3 = fmaxf(t3, __shfl_xor_sync(0xffffffffu, t3, o));
        }
        if (hlane == j) {
            obase[j]            = t0;
            obase[8 * 9 + j]    = t1;
            obase[16 * 9 + j]   = t2;
            obase[24 * 9 + j]   = t3;
        }
    }
}

// ---------------------------------------------------------------------------
extern "C" void kernel_launch(void* const* d_in, const int* in_sizes, int n_in,
                              void* d_out, int out_size) {
    const float* feat = (const float*)d_in[0];
    const void*  mask = d_in[1];
    float* out = (float*)d_out;

    prep_k<<<NCELL, 256>>>(mask);
    dim3 grid(NCELL, F_ / 32, 3);
    pool_k<<<grid, 128>>>(feat, out);
}

// round 10
// speedup vs baseline: 1.1509x; 1.1509x over previous
#include <cuda_runtime.h>
#include <cstdint>
#include <float.h>
#include <limits.h>

// Problem constants (fixed shapes)
#define B_    8
#define C_    16
#define F_    256
#define H_    112
#define W_    112
#define NCELL (B_ * C_)       // 128
#define W4_   (W_ / 4)        // 28 float4 per feature row
#define PXPC  (H_ * W_)       // 12544 pixels per cell

// Compact mask scratch bounds: bbox w <= 35, +3 align +3 pad -> <= 40; h <= 35
#define MAXBW 40
#define MAXBH 36
#define CMSTRIDE (MAXBW * MAXBH)   // 1440 floats

// Per-cell header: y0, szy, x0a, bwa, x0off, szx
__device__ int g_hdr[NCELL][8];
// Per-cell compact float mask (1.0 / 0.0), row stride bwa, 16B aligned rows
__device__ __align__(16) float g_cmask[NCELL][CMSTRIDE];

// ---------------------------------------------------------------------------
// Fused prep: per-cell dtype detect + bbox + compact float mask. 1 block/cell.
__global__ void __launch_bounds__(256) prep_k(const void* __restrict__ mask) {
    const int cell = blockIdx.x;
    const int t = threadIdx.x;

    __shared__ int sy0, sy1, sx0, sx1;
    if (t == 0) { sy0 = INT_MAX; sy1 = -1; sx0 = INT_MAX; sx1 = -1; }

    // --- detect dtype over this cell's 12544-byte window (784 uint4) ---
    int r = 0;
    {
        const uint4* wq = (const uint4*)mask + (size_t)cell * 784;
        for (int i = t; i < 784; i += 256) {
            uint4 w = wq[i];
            if ((w.x != 0x3F800000u && (w.x & 0xFFFFFF00u)) ||
                (w.y != 0x3F800000u && (w.y & 0xFFFFFF00u)) ||
                (w.z != 0x3F800000u && (w.z & 0xFFFFFF00u)) ||
                (w.w != 0x3F800000u && (w.w & 0xFFFFFF00u))) r = 1;
        }
    }
    const int flag = __syncthreads_or(r);

    // --- bbox scan ---
    int ly0 = INT_MAX, ly1 = -1, lx0 = INT_MAX, lx1 = -1;
    if (flag) {
        const uint4* mq = (const uint4*)mask + (size_t)cell * 784;
        for (int i = t; i < 784; i += 256) {
            uint4 w = mq[i];
            if (w.x | w.y | w.z | w.w) {
                int p = i * 16, y = p / W_, xb = p % W_;
                ly0 = min(ly0, y); ly1 = max(ly1, y);
                unsigned int comp[4] = {w.x, w.y, w.z, w.w};
#pragma unroll
                for (int c = 0; c < 4; c++) {
#pragma unroll
                    for (int k = 0; k < 4; k++) {
                        if ((comp[c] >> (k * 8)) & 0xFFu) {
                            int x = xb + c * 4 + k;
                            lx0 = min(lx0, x); lx1 = max(lx1, x);
                        }
                    }
                }
            }
        }
    } else {
        const uint4* mq = (const uint4*)mask + (size_t)cell * 3136;
        for (int i = t; i < 3136; i += 256) {
            uint4 w = mq[i];
            if (w.x | w.y | w.z | w.w) {
                int p = i * 4, y = p / W_, xb = p % W_;
                ly0 = min(ly0, y); ly1 = max(ly1, y);
                if (w.x) { lx0 = min(lx0, xb);     lx1 = max(lx1, xb);     }
                if (w.y) { lx0 = min(lx0, xb + 1); lx1 = max(lx1, xb + 1); }
                if (w.z) { lx0 = min(lx0, xb + 2); lx1 = max(lx1, xb + 2); }
                if (w.w) { lx0 = min(lx0, xb + 3); lx1 = max(lx1, xb + 3); }
            }
        }
    }
    if (ly1 >= 0) {
        atomicMin(&sy0, ly0); atomicMax(&sy1, ly1);
        atomicMin(&sx0, lx0); atomicMax(&sx1, lx1);
    }
    __syncthreads();

    const int y0 = sy0, y1 = sy1 + 1, x0 = sx0, x1 = sx1 + 1;
    const int x0a = x0 & ~3;
    const int bwa = (x1 - x0a + 3) & ~3;
    const int bh  = y1 - y0;

    if (t == 0) {
        g_hdr[cell][0] = y0;
        g_hdr[cell][1] = bh;
        g_hdr[cell][2] = x0a;
        g_hdr[cell][3] = bwa;
        g_hdr[cell][4] = x0 - x0a;
        g_hdr[cell][5] = x1 - x0;
    }

    const int ntot = bh * bwa;
    const uint8_t* mb = (const uint8_t*)mask + (size_t)cell * PXPC;
    const int*     mi = (const int*)mask     + (size_t)cell * PXPC;
    for (int p = t; p < ntot; p += 256) {
        int rr = p / bwa, c = p - rr * bwa;
        int gp = (y0 + rr) * W_ + (x0a + c);
        bool set = flag ? (mb[gp] != 0) : (mi[gp] != 0);
        g_cmask[cell][p] = set ? 1.0f : 0.0f;
    }
}

// ---------------------------------------------------------------------------
// Main pooling. grid=(NCELL, F/32), block=128 (4 warps). Same per-warp
// structure as the best kernel (R6): each half-warp (16 lanes) processes
// FOUR feature streams (f0 + {0,8,16,24}); one LDS.128 mask read feeds 4
// independent LDG.128 feature loads; unroll 2 -> 8 loads in flight per lane
// group. 3 y-bin phases in-block; per phase, x-bins merged and butterfly-
// reduced across the 16-lane group, stored immediately. Half-size blocks
// (1024 total, ~7/SM at 8 CTA/SM) average out per-cell bbox-size variance.
__global__ void __launch_bounds__(128, 8) pool_k(const float* __restrict__ feat,
                                                 float* __restrict__ out) {
    const int cell = blockIdx.x;
    const int warp = threadIdx.x >> 5;
    const int lane = threadIdx.x & 31;
    const int half = lane >> 4;
    const int hlane = lane & 15;
    const int grp = warp * 2 + half;                 // 0..7
    const int f0 = blockIdx.y * 32 + grp;            // streams: f0 + {0,8,16,24}

    const int y0    = g_hdr[cell][0];
    const int szy   = g_hdr[cell][1];
    const int x0a   = g_hdr[cell][2];
    const int bwa   = g_hdr[cell][3];
    const int x0off = g_hdr[cell][4];
    const int szx   = g_hdr[cell][5];

    // --- stage compact mask into shared memory (vectorized) ---
    __shared__ __align__(16) float smask[CMSTRIDE];
    {
        const int nq = (szy * bwa) >> 2;
        const float4* src = (const float4*)g_cmask[cell];
        float4* dst = (float4*)smask;
        for (int p = threadIdx.x; p < nq; p += 128) dst[p] = src[p];
    }
    __syncthreads();

    const int nG  = bwa >> 2;          // float4 groups per row: 3..10
    const int rpi = 16 / nG;           // rows per iteration: 1..5
    const int rowoff = hlane / nG;
    const int g = hlane - rowoff * nG;
    const bool active = (rowoff < rpi);

    const int b = cell >> 4;
    const int FOFF = 8 * H_ * W4_;     // float4 offset between feature streams
    const float4* fbase = (const float4*)feat
        + (size_t)((b * F_ + f0) * H_ + y0) * W4_ + (x0a >> 2) + g;
    const float4* mbase = (const float4*)smask + g;
    const int fstep = rpi * W4_;
    const int mstep = rpi * nG;

    // x-bin membership per (bin j, col k) — phase-invariant
    bool mem[12];
#pragma unroll
    for (int j = 0; j < 3; j++)
#pragma unroll
        for (int k = 0; k < 4; k++) {
            const int relx = g * 4 + k - x0off;
            mem[j * 4 + k] = (3 * relx >= j * szx - 2) && (3 * relx < (j + 1) * szx);
        }

    float* obase = out + (size_t)cell * (F_ * 9) + f0 * 9;

#pragma unroll
    for (int i = 0; i < 3; i++) {
        const int ys = (i * szy) / 3;
        const int ye = ((i + 1) * szy + 2) / 3;   // ceil (bins may share a row)

        float acc[4][4];
#pragma unroll
        for (int s = 0; s < 4; s++)
#pragma unroll
            for (int k = 0; k < 4; k++) acc[s][k] = -FLT_MAX;

        if (active) {
            const float4* fp = fbase + (ys + rowoff) * W4_;
            const float4* mp = mbase + (ys + rowoff) * nG;
#pragma unroll 2
            for (int rr = ys + rowoff; rr < ye; rr += rpi, fp += fstep, mp += mstep) {
                const float4 mv = *mp;          // LDS.128
                float4 fv[4];
                fv[0] = __ldg(fp);
                fv[1] = __ldg(fp + FOFF);
                fv[2] = __ldg(fp + 2 * FOFF);
                fv[3] = __ldg(fp + 3 * FOFF);
#pragma unroll
                for (int s = 0; s < 4; s++) {
                    acc[s][0] = fmaxf(acc[s][0], fv[s].x * mv.x);
                    acc[s][1] = fmaxf(acc[s][1], fv[s].y * mv.y);
                    acc[s][2] = fmaxf(acc[s][2], fv[s].z * mv.z);
                    acc[s][3] = fmaxf(acc[s][3], fv[s].w * mv.w);
                }
            }
        }

        // per x-bin: merge columns, butterfly across the 16-lane group, store
#pragma unroll
        for (int j = 0; j < 3; j++) {
            float t0 = -FLT_MAX, t1 = -FLT_MAX, t2 = -FLT_MAX, t3 = -FLT_MAX;
#pragma unroll
            for (int k = 0; k < 4; k++) {
                if (mem[j * 4 + k]) {
                    t0 = fmaxf(t0, acc[0][k]);
                    t1 = fmaxf(t1, acc[1][k]);
                    t2 = fmaxf(t2, acc[2][k]);
                    t3 = fmaxf(t3, acc[3][k]);
                }
            }
#pragma unroll
            for (int o = 8; o > 0; o >>= 1) {
                t0 = fmaxf(t0, __shfl_xor_sync(0xffffffffu, t0, o));
                t1 = fmaxf(t1, __shfl_xor_sync(0xffffffffu, t1, o));
                t2 = fmaxf(t2, __shfl_xor_sync(0xffffffffu, t2, o));
                t3 = fmaxf(t3, __shfl_xor_sync(0xffffffffu, t3, o));
            }
            if (hlane == j) {
                obase[i * 3 + j]            = t0;
                obase[8 * 9 + i * 3 + j]    = t1;
                obase[16 * 9 + i * 3 + j]   = t2;
                obase[24 * 9 + i * 3 + j]   = t3;
            }
        }
    }
}

// ---------------------------------------------------------------------------
extern "C" void kernel_launch(void* const* d_in, const int* in_sizes, int n_in,
                              void* d_out, int out_size) {
    const float* feat = (const float*)d_in[0];
    const void*  mask = d_in[1];
    float* out = (float*)d_out;

    prep_k<<<NCELL, 256>>>(mask);
    dim3 grid(NCELL, F_ / 32);
    pool_k<<<grid, 128>>>(feat, out);
}